// round 1
// baseline (speedup 1.0000x reference)
#include <cuda_runtime.h>
#include <cuda_bf16.h>
#include <math.h>

// Problem constants (fixed by the dataset)
#define NN 8192      // nodes
#define EE 24576     // edges
#define DD 4         // node feature dim
#define HH 100       // hidden units

// ---------------------------------------------------------------------------
// Device scratch (no allocations allowed in kernel_launch)
// ---------------------------------------------------------------------------
__device__ int   g_idx_i[EE];
__device__ int   g_idx_o[EE];
__device__ float g_mi[NN * DD];
__device__ float g_mo[NN * DD];

// ---------------------------------------------------------------------------
// Kernel 1: zero the scatter accumulators
// ---------------------------------------------------------------------------
__global__ void zero_kernel() {
    int i = blockIdx.x * blockDim.x + threadIdx.x;
    if (i < NN * DD) {
        g_mi[i] = 0.0f;
        g_mo[i] = 0.0f;
    }
}

// ---------------------------------------------------------------------------
// Kernel 2: recover idx_i / idx_o from the dense one-hot incidence matrices.
// Each column of Ri/Ro [N, E] (row-major) has exactly one 1.0; compute
//   fidx = sum_r r * M[r, c],  found = sum_r M[r, c]
// over a row-chunk. Exactly one (block-row) chunk finds the 1.0 per column,
// so the writer is unique -> plain store, no atomics.
//
// Layout: 256 threads * float4 = 1024 consecutive columns per block.x
//         blockIdx.y = row chunk (ROWS_PER_CHUNK rows)
//         blockIdx.z = 0 -> Ri, 1 -> Ro
// ---------------------------------------------------------------------------
#define SCAN_THREADS     256
#define COLS_PER_BLOCK   (SCAN_THREADS * 4)      // 1024
#define ROW_CHUNKS       64
#define ROWS_PER_CHUNK   (NN / ROW_CHUNKS)       // 128

__global__ __launch_bounds__(SCAN_THREADS)
void find_idx_kernel(const float* __restrict__ Ri, const float* __restrict__ Ro) {
    const float* M   = (blockIdx.z == 0) ? Ri : Ro;
    int*         out = (blockIdx.z == 0) ? g_idx_i : g_idx_o;

    const int col = blockIdx.x * COLS_PER_BLOCK + threadIdx.x * 4;
    const int r0  = blockIdx.y * ROWS_PER_CHUNK;

    const float4* p = reinterpret_cast<const float4*>(M + (long)r0 * EE + col);
    const int row_stride4 = EE / 4;  // float4 elements per row

    float fi0 = 0.f, fi1 = 0.f, fi2 = 0.f, fi3 = 0.f;
    float ff0 = 0.f, ff1 = 0.f, ff2 = 0.f, ff3 = 0.f;

    #pragma unroll 8
    for (int r = 0; r < ROWS_PER_CHUNK; ++r) {
        float4 v = __ldcs(p + (long)r * row_stride4);   // streaming: evict-first
        float fr = (float)(r0 + r);
        fi0 = fmaf(v.x, fr, fi0); ff0 += v.x;
        fi1 = fmaf(v.y, fr, fi1); ff1 += v.y;
        fi2 = fmaf(v.z, fr, fi2); ff2 += v.z;
        fi3 = fmaf(v.w, fr, fi3); ff3 += v.w;
    }

    if (ff0 != 0.f) out[col + 0] = (int)fi0;
    if (ff1 != 0.f) out[col + 1] = (int)fi1;
    if (ff2 != 0.f) out[col + 2] = (int)fi2;
    if (ff3 != 0.f) out[col + 3] = (int)fi3;
}

// ---------------------------------------------------------------------------
// Kernel 3: per-edge weighted scatter
//   mi[idx_i[k]] += e[k] * X[idx_o[k]]
//   mo[idx_o[k]] += e[k] * X[idx_i[k]]
// ---------------------------------------------------------------------------
__global__ void scatter_kernel(const float* __restrict__ X,
                               const float* __restrict__ e) {
    int k = blockIdx.x * blockDim.x + threadIdx.x;
    if (k >= EE) return;

    int   ii = g_idx_i[k];
    int   io = g_idx_o[k];
    float ek = e[k];

    float4 xo = reinterpret_cast<const float4*>(X)[io];
    float4 xi = reinterpret_cast<const float4*>(X)[ii];

    float* mi = g_mi + 4 * ii;
    atomicAdd(mi + 0, ek * xo.x);
    atomicAdd(mi + 1, ek * xo.y);
    atomicAdd(mi + 2, ek * xo.z);
    atomicAdd(mi + 3, ek * xo.w);

    float* mo = g_mo + 4 * io;
    atomicAdd(mo + 0, ek * xi.x);
    atomicAdd(mo + 1, ek * xi.y);
    atomicAdd(mo + 2, ek * xi.z);
    atomicAdd(mo + 3, ek * xi.w);
}

// ---------------------------------------------------------------------------
// Kernel 4: fused MLP  out = sigmoid( tanh([mi,mo,X] @ W1 + b1) @ W2 + b2 )
// One thread per node; weights staged in shared memory.
// ---------------------------------------------------------------------------
#define MLP_THREADS 256

__global__ __launch_bounds__(MLP_THREADS)
void mlp_kernel(const float* __restrict__ X,
                const float* __restrict__ W1, const float* __restrict__ b1,
                const float* __restrict__ W2, const float* __restrict__ b2,
                float* __restrict__ out) {
    __shared__ float sW1[3 * DD * HH];   // [12][100] row-major
    __shared__ float sb1[HH];
    __shared__ float sW2[HH];
    __shared__ float sb2;

    for (int i = threadIdx.x; i < 3 * DD * HH; i += MLP_THREADS) sW1[i] = W1[i];
    for (int i = threadIdx.x; i < HH; i += MLP_THREADS) {
        sb1[i] = b1[i];
        sW2[i] = W2[i];
    }
    if (threadIdx.x == 0) sb2 = b2[0];
    __syncthreads();

    int n = blockIdx.x * MLP_THREADS + threadIdx.x;
    if (n >= NN) return;

    float in[3 * DD];
    float4 a = reinterpret_cast<const float4*>(g_mi)[n];
    float4 b = reinterpret_cast<const float4*>(g_mo)[n];
    float4 c = reinterpret_cast<const float4*>(X)[n];
    in[0] = a.x; in[1] = a.y; in[2]  = a.z; in[3]  = a.w;
    in[4] = b.x; in[5] = b.y; in[6]  = b.z; in[7]  = b.w;
    in[8] = c.x; in[9] = c.y; in[10] = c.z; in[11] = c.w;

    float acc = sb2;
    for (int j = 0; j < HH; ++j) {
        float s = sb1[j];
        #pragma unroll
        for (int i = 0; i < 3 * DD; ++i)
            s = fmaf(in[i], sW1[i * HH + j], s);
        acc = fmaf(tanhf(s), sW2[j], acc);
    }
    out[n] = 1.0f / (1.0f + expf(-acc));
}

// ---------------------------------------------------------------------------
// Launch
// Inputs (metadata order): X, e, Ri, Ro, W1, b1, W2, b2
// ---------------------------------------------------------------------------
extern "C" void kernel_launch(void* const* d_in, const int* in_sizes, int n_in,
                              void* d_out, int out_size) {
    const float* X  = (const float*)d_in[0];
    const float* e  = (const float*)d_in[1];
    const float* Ri = (const float*)d_in[2];
    const float* Ro = (const float*)d_in[3];
    const float* W1 = (const float*)d_in[4];
    const float* b1 = (const float*)d_in[5];
    const float* W2 = (const float*)d_in[6];
    const float* b2 = (const float*)d_in[7];
    float* out = (float*)d_out;

    // 1) zero accumulators
    zero_kernel<<<(NN * DD + 255) / 256, 256>>>();

    // 2) recover indices from dense one-hot matrices (the HBM-bound part)
    dim3 grid(EE / COLS_PER_BLOCK, ROW_CHUNKS, 2);   // (24, 64, 2) = 3072 blocks
    find_idx_kernel<<<grid, SCAN_THREADS>>>(Ri, Ro);

    // 3) per-edge scatter
    scatter_kernel<<<(EE + 255) / 256, 256>>>(X, e);

    // 4) fused MLP
    mlp_kernel<<<(NN + MLP_THREADS - 1) / MLP_THREADS, MLP_THREADS>>>(
        X, W1, b1, W2, b2, out);
}

// round 2
// speedup vs baseline: 1.0138x; 1.0138x over previous
#include <cuda_runtime.h>
#include <cuda_bf16.h>
#include <math.h>

// Problem constants (fixed by the dataset)
#define NN 8192      // nodes
#define EE 24576     // edges
#define DD 4         // node feature dim
#define HH 100       // hidden units

// ---------------------------------------------------------------------------
// Device scratch (no allocations allowed in kernel_launch)
// ---------------------------------------------------------------------------
__device__ int   g_idx_i[EE];
__device__ int   g_idx_o[EE];
__device__ float g_mi[NN * DD];
__device__ float g_mo[NN * DD];

// ---------------------------------------------------------------------------
// Kernel 1: zero the scatter accumulators
// ---------------------------------------------------------------------------
__global__ void zero_kernel() {
    int i = blockIdx.x * blockDim.x + threadIdx.x;
    if (i < NN * DD) {
        g_mi[i] = 0.0f;
        g_mo[i] = 0.0f;
    }
}

// ---------------------------------------------------------------------------
// Kernel 2: recover idx_i / idx_o from the dense one-hot incidence matrices.
// Each column of Ri/Ro [N, E] (row-major) has exactly one 1.0; compute
//   fidx = sum_r r * M[r, c],  found = sum_r M[r, c]
// over a row-chunk. Exactly one (block-row) chunk finds the 1.0 per column,
// so the writer is unique -> plain store, no atomics.
// This kernel is the HBM roofline: 2 * N * E * 4B = 1.61 GB streamed once.
// ---------------------------------------------------------------------------
#define SCAN_THREADS     256
#define COLS_PER_BLOCK   (SCAN_THREADS * 4)      // 1024
#define ROW_CHUNKS       64
#define ROWS_PER_CHUNK   (NN / ROW_CHUNKS)       // 128

__global__ __launch_bounds__(SCAN_THREADS)
void find_idx_kernel(const float* __restrict__ Ri, const float* __restrict__ Ro) {
    const float* M   = (blockIdx.z == 0) ? Ri : Ro;
    int*         out = (blockIdx.z == 0) ? g_idx_i : g_idx_o;

    const int col = blockIdx.x * COLS_PER_BLOCK + threadIdx.x * 4;
    const int r0  = blockIdx.y * ROWS_PER_CHUNK;

    const float4* p = reinterpret_cast<const float4*>(M + (long)r0 * EE + col);
    const int row_stride4 = EE / 4;  // float4 elements per row

    float fi0 = 0.f, fi1 = 0.f, fi2 = 0.f, fi3 = 0.f;
    float ff0 = 0.f, ff1 = 0.f, ff2 = 0.f, ff3 = 0.f;

    #pragma unroll 16
    for (int r = 0; r < ROWS_PER_CHUNK; ++r) {
        float4 v = __ldcs(p + (long)r * row_stride4);   // streaming: evict-first
        float fr = (float)(r0 + r);
        fi0 = fmaf(v.x, fr, fi0); ff0 += v.x;
        fi1 = fmaf(v.y, fr, fi1); ff1 += v.y;
        fi2 = fmaf(v.z, fr, fi2); ff2 += v.z;
        fi3 = fmaf(v.w, fr, fi3); ff3 += v.w;
    }

    if (ff0 != 0.f) out[col + 0] = (int)fi0;
    if (ff1 != 0.f) out[col + 1] = (int)fi1;
    if (ff2 != 0.f) out[col + 2] = (int)fi2;
    if (ff3 != 0.f) out[col + 3] = (int)fi3;
}

// ---------------------------------------------------------------------------
// Kernel 3: per-edge weighted scatter
//   mi[idx_i[k]] += e[k] * X[idx_o[k]]
//   mo[idx_o[k]] += e[k] * X[idx_i[k]]
// ---------------------------------------------------------------------------
__global__ void scatter_kernel(const float* __restrict__ X,
                               const float* __restrict__ e) {
    int k = blockIdx.x * blockDim.x + threadIdx.x;
    if (k >= EE) return;

    int   ii = g_idx_i[k];
    int   io = g_idx_o[k];
    float ek = e[k];

    float4 xo = reinterpret_cast<const float4*>(X)[io];
    float4 xi = reinterpret_cast<const float4*>(X)[ii];

    float* mi = g_mi + 4 * ii;
    atomicAdd(mi + 0, ek * xo.x);
    atomicAdd(mi + 1, ek * xo.y);
    atomicAdd(mi + 2, ek * xo.z);
    atomicAdd(mi + 3, ek * xo.w);

    float* mo = g_mo + 4 * io;
    atomicAdd(mo + 0, ek * xi.x);
    atomicAdd(mo + 1, ek * xi.y);
    atomicAdd(mo + 2, ek * xi.z);
    atomicAdd(mo + 3, ek * xi.w);
}

// ---------------------------------------------------------------------------
// Fast device math
// ---------------------------------------------------------------------------
__device__ __forceinline__ float fast_tanh(float x) {
    float y;
    asm("tanh.approx.f32 %0, %1;" : "=f"(y) : "f"(x));
    return y;
}

// ---------------------------------------------------------------------------
// Kernel 4: fused MLP  out = sigmoid( tanh([mi,mo,X] @ W1 + b1) @ W2 + b2 )
// 4 threads per node, 25 hidden units each, shfl reduce. tanh.approx (MUFU).
// ---------------------------------------------------------------------------
#define MLP_THREADS 256
#define TPN 4                 // threads per node
#define HPT (HH / TPN)        // 25 hidden units per thread

__global__ __launch_bounds__(MLP_THREADS)
void mlp_kernel(const float* __restrict__ X,
                const float* __restrict__ W1, const float* __restrict__ b1,
                const float* __restrict__ W2, const float* __restrict__ b2,
                float* __restrict__ out) {
    __shared__ float sW1[3 * DD * HH];   // [12][100] row-major
    __shared__ float sb1[HH];
    __shared__ float sW2[HH];

    for (int i = threadIdx.x; i < 3 * DD * HH; i += MLP_THREADS) sW1[i] = W1[i];
    for (int i = threadIdx.x; i < HH; i += MLP_THREADS) {
        sb1[i] = b1[i];
        sW2[i] = W2[i];
    }
    __syncthreads();

    int t = blockIdx.x * MLP_THREADS + threadIdx.x;
    int n = t / TPN;          // node
    int q = t % TPN;          // quarter of hidden units
    if (n >= NN) return;

    float in[3 * DD];
    float4 a = reinterpret_cast<const float4*>(g_mi)[n];
    float4 b = reinterpret_cast<const float4*>(g_mo)[n];
    float4 c = reinterpret_cast<const float4*>(X)[n];
    in[0] = a.x; in[1] = a.y; in[2]  = a.z; in[3]  = a.w;
    in[4] = b.x; in[5] = b.y; in[6]  = b.z; in[7]  = b.w;
    in[8] = c.x; in[9] = c.y; in[10] = c.z; in[11] = c.w;

    float acc = 0.0f;
    const int j0 = q * HPT;
    #pragma unroll 5
    for (int jj = 0; jj < HPT; ++jj) {
        const int j = j0 + jj;
        float s = sb1[j];
        #pragma unroll
        for (int i = 0; i < 3 * DD; ++i)
            s = fmaf(in[i], sW1[i * HH + j], s);
        acc = fmaf(fast_tanh(s), sW2[j], acc);
    }

    // reduce the 4 partial sums within the node's thread quad
    acc += __shfl_xor_sync(0xFFFFFFFFu, acc, 1);
    acc += __shfl_xor_sync(0xFFFFFFFFu, acc, 2);

    if (q == 0) {
        acc += b2[0];
        out[n] = 1.0f / (1.0f + __expf(-acc));
    }
}

// ---------------------------------------------------------------------------
// Launch
// Inputs (metadata order): X, e, Ri, Ro, W1, b1, W2, b2
// ---------------------------------------------------------------------------
extern "C" void kernel_launch(void* const* d_in, const int* in_sizes, int n_in,
                              void* d_out, int out_size) {
    const float* X  = (const float*)d_in[0];
    const float* e  = (const float*)d_in[1];
    const float* Ri = (const float*)d_in[2];
    const float* Ro = (const float*)d_in[3];
    const float* W1 = (const float*)d_in[4];
    const float* b1 = (const float*)d_in[5];
    const float* W2 = (const float*)d_in[6];
    const float* b2 = (const float*)d_in[7];
    float* out = (float*)d_out;

    // 1) zero accumulators
    zero_kernel<<<(NN * DD + 255) / 256, 256>>>();

    // 2) recover indices from dense one-hot matrices (the HBM-bound part)
    dim3 grid(EE / COLS_PER_BLOCK, ROW_CHUNKS, 2);   // (24, 64, 2) = 3072 blocks
    find_idx_kernel<<<grid, SCAN_THREADS>>>(Ri, Ro);

    // 3) per-edge scatter
    scatter_kernel<<<(EE + 255) / 256, 256>>>(X, e);

    // 4) fused MLP (4 threads/node, tanh.approx)
    mlp_kernel<<<(NN * TPN + MLP_THREADS - 1) / MLP_THREADS, MLP_THREADS>>>(
        X, W1, b1, W2, b2, out);
}

// round 3
// speedup vs baseline: 1.0265x; 1.0126x over previous
#include <cuda_runtime.h>
#include <cuda_bf16.h>
#include <math.h>

// Problem constants (fixed by the dataset)
#define NN 8192      // nodes
#define EE 24576     // edges
#define DD 4         // node feature dim
#define HH 100       // hidden units

// ---------------------------------------------------------------------------
// Device scratch (no allocations allowed in kernel_launch)
// ---------------------------------------------------------------------------
__device__ int   g_idx_i[EE];
__device__ int   g_idx_o[EE];
__device__ float g_mi[NN * DD];
__device__ float g_mo[NN * DD];

// ---------------------------------------------------------------------------
// Kernel 1: recover idx_i / idx_o from the dense one-hot incidence matrices,
// and (prologue, subset of blocks) zero the scatter accumulators.
//
// Each column of Ri/Ro [N, E] (row-major) has exactly one 1.0; compute
//   fidx = sum_r r * M[r, c],  found = sum_r M[r, c]
// over a row-chunk. Exactly one (block-row) chunk finds the 1.0 per column,
// so the writer is unique -> plain store, no atomics.
// This kernel is the HBM roofline: 2 * N * E * 4B = 1.61 GB streamed once.
// ---------------------------------------------------------------------------
#define SCAN_THREADS     256
#define COLS_PER_BLOCK   (SCAN_THREADS * 4)      // 1024
#define ROW_CHUNKS       64
#define ROWS_PER_CHUNK   (NN / ROW_CHUNKS)       // 128

__global__ __launch_bounds__(SCAN_THREADS)
void find_idx_kernel(const float* __restrict__ Ri, const float* __restrict__ Ro) {
    // --- prologue: zero g_mi / g_mo (completes before scatter_kernel via
    //     kernel-boundary ordering). 24 x 8 blocks * 256 thr * 2 = 98304 slots
    //     cover the 2 * 32768 floats.
    if (blockIdx.z == 0 && blockIdx.y < 8) {
        int t = (blockIdx.y * gridDim.x + blockIdx.x) * SCAN_THREADS + threadIdx.x;
        if (t < NN * DD) { g_mi[t] = 0.0f; g_mo[t] = 0.0f; }
    }

    const float* M   = (blockIdx.z == 0) ? Ri : Ro;
    int*         out = (blockIdx.z == 0) ? g_idx_i : g_idx_o;

    const int col = blockIdx.x * COLS_PER_BLOCK + threadIdx.x * 4;
    const int r0  = blockIdx.y * ROWS_PER_CHUNK;

    const float4* p = reinterpret_cast<const float4*>(M + (long)r0 * EE + col);
    const int row_stride4 = EE / 4;  // float4 elements per row

    float fi0 = 0.f, fi1 = 0.f, fi2 = 0.f, fi3 = 0.f;
    float ff0 = 0.f, ff1 = 0.f, ff2 = 0.f, ff3 = 0.f;

    #pragma unroll 16
    for (int r = 0; r < ROWS_PER_CHUNK; ++r) {
        float4 v = __ldcs(p + (long)r * row_stride4);   // streaming: evict-first
        float fr = (float)(r0 + r);
        fi0 = fmaf(v.x, fr, fi0); ff0 += v.x;
        fi1 = fmaf(v.y, fr, fi1); ff1 += v.y;
        fi2 = fmaf(v.z, fr, fi2); ff2 += v.z;
        fi3 = fmaf(v.w, fr, fi3); ff3 += v.w;
    }

    if (ff0 != 0.f) out[col + 0] = (int)fi0;
    if (ff1 != 0.f) out[col + 1] = (int)fi1;
    if (ff2 != 0.f) out[col + 2] = (int)fi2;
    if (ff3 != 0.f) out[col + 3] = (int)fi3;
}

// ---------------------------------------------------------------------------
// Kernel 2: per-edge weighted scatter
//   mi[idx_i[k]] += e[k] * X[idx_o[k]]
//   mo[idx_o[k]] += e[k] * X[idx_i[k]]
// ---------------------------------------------------------------------------
__global__ void scatter_kernel(const float* __restrict__ X,
                               const float* __restrict__ e) {
    int k = blockIdx.x * blockDim.x + threadIdx.x;
    if (k >= EE) return;

    int   ii = g_idx_i[k];
    int   io = g_idx_o[k];
    float ek = e[k];

    float4 xo = reinterpret_cast<const float4*>(X)[io];
    float4 xi = reinterpret_cast<const float4*>(X)[ii];

    float* mi = g_mi + 4 * ii;
    atomicAdd(mi + 0, ek * xo.x);
    atomicAdd(mi + 1, ek * xo.y);
    atomicAdd(mi + 2, ek * xo.z);
    atomicAdd(mi + 3, ek * xo.w);

    float* mo = g_mo + 4 * io;
    atomicAdd(mo + 0, ek * xi.x);
    atomicAdd(mo + 1, ek * xi.y);
    atomicAdd(mo + 2, ek * xi.z);
    atomicAdd(mo + 3, ek * xi.w);
}

// ---------------------------------------------------------------------------
// Fast device math
// ---------------------------------------------------------------------------
__device__ __forceinline__ float fast_tanh(float x) {
    float y;
    asm("tanh.approx.f32 %0, %1;" : "=f"(y) : "f"(x));
    return y;
}

// ---------------------------------------------------------------------------
// Kernel 3: fused MLP  out = sigmoid( tanh([mi,mo,X] @ W1 + b1) @ W2 + b2 )
// 4 threads per node, 25 hidden units each, shfl reduce, tanh.approx (MUFU).
// Block = 128 threads -> grid = 256 blocks so every SM gets work.
// ---------------------------------------------------------------------------
#define MLP_THREADS 128
#define TPN 4                 // threads per node
#define HPT (HH / TPN)        // 25 hidden units per thread

__global__ __launch_bounds__(MLP_THREADS)
void mlp_kernel(const float* __restrict__ X,
                const float* __restrict__ W1, const float* __restrict__ b1,
                const float* __restrict__ W2, const float* __restrict__ b2,
                float* __restrict__ out) {
    __shared__ float sW1[3 * DD * HH];   // [12][100] row-major
    __shared__ float sb1[HH];
    __shared__ float sW2[HH];

    for (int i = threadIdx.x; i < 3 * DD * HH; i += MLP_THREADS) sW1[i] = W1[i];
    for (int i = threadIdx.x; i < HH; i += MLP_THREADS) {
        sb1[i] = b1[i];
        sW2[i] = W2[i];
    }
    __syncthreads();

    int t = blockIdx.x * MLP_THREADS + threadIdx.x;
    int n = t / TPN;          // node
    int q = t % TPN;          // quarter of hidden units
    if (n >= NN) return;

    float in[3 * DD];
    float4 a = reinterpret_cast<const float4*>(g_mi)[n];
    float4 b = reinterpret_cast<const float4*>(g_mo)[n];
    float4 c = reinterpret_cast<const float4*>(X)[n];
    in[0] = a.x; in[1] = a.y; in[2]  = a.z; in[3]  = a.w;
    in[4] = b.x; in[5] = b.y; in[6]  = b.z; in[7]  = b.w;
    in[8] = c.x; in[9] = c.y; in[10] = c.z; in[11] = c.w;

    float acc = 0.0f;
    const int j0 = q * HPT;
    #pragma unroll 5
    for (int jj = 0; jj < HPT; ++jj) {
        const int j = j0 + jj;
        float s = sb1[j];
        #pragma unroll
        for (int i = 0; i < 3 * DD; ++i)
            s = fmaf(in[i], sW1[i * HH + j], s);
        acc = fmaf(fast_tanh(s), sW2[j], acc);
    }

    // reduce the 4 partial sums within the node's thread quad
    acc += __shfl_xor_sync(0xFFFFFFFFu, acc, 1);
    acc += __shfl_xor_sync(0xFFFFFFFFu, acc, 2);

    if (q == 0) {
        acc += b2[0];
        out[n] = 1.0f / (1.0f + __expf(-acc));
    }
}

// ---------------------------------------------------------------------------
// Launch
// Inputs (metadata order): X, e, Ri, Ro, W1, b1, W2, b2
// ---------------------------------------------------------------------------
extern "C" void kernel_launch(void* const* d_in, const int* in_sizes, int n_in,
                              void* d_out, int out_size) {
    const float* X  = (const float*)d_in[0];
    const float* e  = (const float*)d_in[1];
    const float* Ri = (const float*)d_in[2];
    const float* Ro = (const float*)d_in[3];
    const float* W1 = (const float*)d_in[4];
    const float* b1 = (const float*)d_in[5];
    const float* W2 = (const float*)d_in[6];
    const float* b2 = (const float*)d_in[7];
    float* out = (float*)d_out;

    // 1) recover indices from dense one-hot matrices (HBM-bound) + zero accs
    dim3 grid(EE / COLS_PER_BLOCK, ROW_CHUNKS, 2);   // (24, 64, 2) = 3072 blocks
    find_idx_kernel<<<grid, SCAN_THREADS>>>(Ri, Ro);

    // 2) per-edge scatter
    scatter_kernel<<<(EE + 255) / 256, 256>>>(X, e);

    // 3) fused MLP (4 threads/node, 256 blocks)
    mlp_kernel<<<(NN * TPN + MLP_THREADS - 1) / MLP_THREADS, MLP_THREADS>>>(
        X, W1, b1, W2, b2, out);
}

// round 4
// speedup vs baseline: 1.0348x; 1.0081x over previous
#include <cuda_runtime.h>
#include <cuda_bf16.h>
#include <math.h>

// Problem constants (fixed by the dataset)
#define NN 8192      // nodes
#define EE 24576     // edges
#define DD 4         // node feature dim
#define HH 100       // hidden units

// ---------------------------------------------------------------------------
// Device scratch (no allocations allowed in kernel_launch)
// ---------------------------------------------------------------------------
__device__ int   g_idx_i[EE];
__device__ int   g_idx_o[EE];
__device__ float g_mi[NN * DD];
__device__ float g_mo[NN * DD];

// ---------------------------------------------------------------------------
// Kernel 1: recover idx_i / idx_o from the dense one-hot incidence matrices,
// and (prologue, subset of blocks) zero the scatter accumulators.
//
// Each column of Ri/Ro [N, E] (row-major) has exactly one 1.0; compute
//   fidx = sum_r r * M[r, c],  found = sum_r M[r, c]
// over a row-chunk. Exactly one (block-row) chunk finds the 1.0 per column,
// so the writer is unique -> plain store, no atomics.
// This kernel is the HBM roofline: 2 * N * E * 4B = 1.61 GB streamed once.
//
// R4: explicit 8-deep float4 load batching (32 load regs in flight) with a
// 64-reg budget so ptxas keeps MLP high; 4 blocks/SM = 32 warps/SM.
// ---------------------------------------------------------------------------
#define SCAN_THREADS     256
#define COLS_PER_BLOCK   (SCAN_THREADS * 4)      // 1024
#define ROW_CHUNKS       64
#define ROWS_PER_CHUNK   (NN / ROW_CHUNKS)       // 128
#define BATCH            8

__global__ __launch_bounds__(SCAN_THREADS, 4)
void find_idx_kernel(const float* __restrict__ Ri, const float* __restrict__ Ro) {
    // --- prologue: zero g_mi / g_mo (completes before scatter_kernel via
    //     kernel-boundary ordering).
    if (blockIdx.z == 0 && blockIdx.y < 8) {
        int t = (blockIdx.y * gridDim.x + blockIdx.x) * SCAN_THREADS + threadIdx.x;
        if (t < NN * DD) { g_mi[t] = 0.0f; g_mo[t] = 0.0f; }
    }

    const float* M   = (blockIdx.z == 0) ? Ri : Ro;
    int*         out = (blockIdx.z == 0) ? g_idx_i : g_idx_o;

    const int col = blockIdx.x * COLS_PER_BLOCK + threadIdx.x * 4;
    const int r0  = blockIdx.y * ROWS_PER_CHUNK;

    const float4* p = reinterpret_cast<const float4*>(M + (long)r0 * EE + col);
    const int row_stride4 = EE / 4;  // float4 elements per row

    float fi0 = 0.f, fi1 = 0.f, fi2 = 0.f, fi3 = 0.f;
    float ff0 = 0.f, ff1 = 0.f, ff2 = 0.f, ff3 = 0.f;

    for (int rb = 0; rb < ROWS_PER_CHUNK; rb += BATCH) {
        // front-batch BATCH independent LDG.128s (deep MLP)
        float4 v[BATCH];
        #pragma unroll
        for (int j = 0; j < BATCH; ++j)
            v[j] = __ldcs(p + (long)(rb + j) * row_stride4);   // streaming

        #pragma unroll
        for (int j = 0; j < BATCH; ++j) {
            float fr = (float)(r0 + rb + j);
            fi0 = fmaf(v[j].x, fr, fi0); ff0 += v[j].x;
            fi1 = fmaf(v[j].y, fr, fi1); ff1 += v[j].y;
            fi2 = fmaf(v[j].z, fr, fi2); ff2 += v[j].z;
            fi3 = fmaf(v[j].w, fr, fi3); ff3 += v[j].w;
        }
    }

    if (ff0 != 0.f) out[col + 0] = (int)fi0;
    if (ff1 != 0.f) out[col + 1] = (int)fi1;
    if (ff2 != 0.f) out[col + 2] = (int)fi2;
    if (ff3 != 0.f) out[col + 3] = (int)fi3;
}

// ---------------------------------------------------------------------------
// Kernel 2: per-edge weighted scatter
//   mi[idx_i[k]] += e[k] * X[idx_o[k]]
//   mo[idx_o[k]] += e[k] * X[idx_i[k]]
// ---------------------------------------------------------------------------
__global__ void scatter_kernel(const float* __restrict__ X,
                               const float* __restrict__ e) {
    int k = blockIdx.x * blockDim.x + threadIdx.x;
    if (k >= EE) return;

    int   ii = g_idx_i[k];
    int   io = g_idx_o[k];
    float ek = e[k];

    float4 xo = reinterpret_cast<const float4*>(X)[io];
    float4 xi = reinterpret_cast<const float4*>(X)[ii];

    float* mi = g_mi + 4 * ii;
    atomicAdd(mi + 0, ek * xo.x);
    atomicAdd(mi + 1, ek * xo.y);
    atomicAdd(mi + 2, ek * xo.z);
    atomicAdd(mi + 3, ek * xo.w);

    float* mo = g_mo + 4 * io;
    atomicAdd(mo + 0, ek * xi.x);
    atomicAdd(mo + 1, ek * xi.y);
    atomicAdd(mo + 2, ek * xi.z);
    atomicAdd(mo + 3, ek * xi.w);
}

// ---------------------------------------------------------------------------
// Fast device math
// ---------------------------------------------------------------------------
__device__ __forceinline__ float fast_tanh(float x) {
    float y;
    asm("tanh.approx.f32 %0, %1;" : "=f"(y) : "f"(x));
    return y;
}

// ---------------------------------------------------------------------------
// Kernel 3: fused MLP  out = sigmoid( tanh([mi,mo,X] @ W1 + b1) @ W2 + b2 )
// 4 threads per node, 25 hidden units each, shfl reduce, tanh.approx (MUFU).
// ---------------------------------------------------------------------------
#define MLP_THREADS 128
#define TPN 4                 // threads per node
#define HPT (HH / TPN)        // 25 hidden units per thread

__global__ __launch_bounds__(MLP_THREADS)
void mlp_kernel(const float* __restrict__ X,
                const float* __restrict__ W1, const float* __restrict__ b1,
                const float* __restrict__ W2, const float* __restrict__ b2,
                float* __restrict__ out) {
    __shared__ float sW1[3 * DD * HH];   // [12][100] row-major
    __shared__ float sb1[HH];
    __shared__ float sW2[HH];

    for (int i = threadIdx.x; i < 3 * DD * HH; i += MLP_THREADS) sW1[i] = W1[i];
    for (int i = threadIdx.x; i < HH; i += MLP_THREADS) {
        sb1[i] = b1[i];
        sW2[i] = W2[i];
    }
    __syncthreads();

    int t = blockIdx.x * MLP_THREADS + threadIdx.x;
    int n = t / TPN;          // node
    int q = t % TPN;          // quarter of hidden units
    if (n >= NN) return;

    float in[3 * DD];
    float4 a = reinterpret_cast<const float4*>(g_mi)[n];
    float4 b = reinterpret_cast<const float4*>(g_mo)[n];
    float4 c = reinterpret_cast<const float4*>(X)[n];
    in[0] = a.x; in[1] = a.y; in[2]  = a.z; in[3]  = a.w;
    in[4] = b.x; in[5] = b.y; in[6]  = b.z; in[7]  = b.w;
    in[8] = c.x; in[9] = c.y; in[10] = c.z; in[11] = c.w;

    float acc = 0.0f;
    const int j0 = q * HPT;
    #pragma unroll 5
    for (int jj = 0; jj < HPT; ++jj) {
        const int j = j0 + jj;
        float s = sb1[j];
        #pragma unroll
        for (int i = 0; i < 3 * DD; ++i)
            s = fmaf(in[i], sW1[i * HH + j], s);
        acc = fmaf(fast_tanh(s), sW2[j], acc);
    }

    // reduce the 4 partial sums within the node's thread quad
    acc += __shfl_xor_sync(0xFFFFFFFFu, acc, 1);
    acc += __shfl_xor_sync(0xFFFFFFFFu, acc, 2);

    if (q == 0) {
        acc += b2[0];
        out[n] = 1.0f / (1.0f + __expf(-acc));
    }
}

// ---------------------------------------------------------------------------
// Launch
// Inputs (metadata order): X, e, Ri, Ro, W1, b1, W2, b2
// ---------------------------------------------------------------------------
extern "C" void kernel_launch(void* const* d_in, const int* in_sizes, int n_in,
                              void* d_out, int out_size) {
    const float* X  = (const float*)d_in[0];
    const float* e  = (const float*)d_in[1];
    const float* Ri = (const float*)d_in[2];
    const float* Ro = (const float*)d_in[3];
    const float* W1 = (const float*)d_in[4];
    const float* b1 = (const float*)d_in[5];
    const float* W2 = (const float*)d_in[6];
    const float* b2 = (const float*)d_in[7];
    float* out = (float*)d_out;

    // 1) recover indices from dense one-hot matrices (HBM-bound) + zero accs
    dim3 grid(EE / COLS_PER_BLOCK, ROW_CHUNKS, 2);   // (24, 64, 2) = 3072 blocks
    find_idx_kernel<<<grid, SCAN_THREADS>>>(Ri, Ro);

    // 2) per-edge scatter
    scatter_kernel<<<(EE + 255) / 256, 256>>>(X, e);

    // 3) fused MLP (4 threads/node, 256 blocks)
    mlp_kernel<<<(NN * TPN + MLP_THREADS - 1) / MLP_THREADS, MLP_THREADS>>>(
        X, W1, b1, W2, b2, out);
}